// round 2
// baseline (speedup 1.0000x reference)
#include <cuda_runtime.h>
#include <cstdint>

#define GN 8192   // number of graph nodes

// ---------------------------------------------------------------------------
// Scratch (device globals: allocation-free per harness rules)
// ---------------------------------------------------------------------------
__device__ float g_dinv[GN];          // rsqrt(1 + rowsum(adj))
__device__ float g_Zs[GN * 128];      // dinv ⊙ (h @ W), max width 128
__device__ float g_H[GN * 128];       // layer activations

// ---------------------------------------------------------------------------
// Kernel 1: dinv[i] = rsqrt(1 + sum_k adj[i,k])   (A_hat = adj + I row sums)
// ---------------------------------------------------------------------------
__global__ void rowsum_kernel(const float* __restrict__ adj) {
    int row = blockIdx.x;
    const float4* p = reinterpret_cast<const float4*>(adj + (size_t)row * GN);
    float s = 0.f;
    for (int i = threadIdx.x; i < GN / 4; i += blockDim.x) {
        float4 v = p[i];
        s += (v.x + v.y) + (v.z + v.w);
    }
    __shared__ float red[8];
    #pragma unroll
    for (int o = 16; o; o >>= 1) s += __shfl_down_sync(0xffffffffu, s, o);
    if ((threadIdx.x & 31) == 0) red[threadIdx.x >> 5] = s;
    __syncthreads();
    if (threadIdx.x == 0) {
        float t = 0.f;
        #pragma unroll
        for (int w = 0; w < 8; w++) t += red[w];
        g_dinv[row] = rsqrtf(t + 1.0f);
    }
}

// ---------------------------------------------------------------------------
// Kernel 2: Zs = dinv ⊙ (Hin @ W)   (small feature GEMM, M=8192, K<=128, N<=128)
// ---------------------------------------------------------------------------
template<int K, int NC, bool FROM_PARAM>
__global__ void feat_gemm_kernel(const float* __restrict__ Xin,
                                 const float* __restrict__ W) {
    const int ROWS = 32;
    __shared__ float hs[ROWS][K];
    const float* Hin = FROM_PARAM ? Xin : g_H;
    int row0 = blockIdx.x * ROWS;
    int j = threadIdx.x;   // output column (blockDim.x == NC)

    const float4* src = reinterpret_cast<const float4*>(Hin + (size_t)row0 * K);
    float4* dst = reinterpret_cast<float4*>(&hs[0][0]);
    for (int i = threadIdx.x; i < ROWS * K / 4; i += NC) dst[i] = src[i];
    __syncthreads();

    for (int r0 = 0; r0 < ROWS; r0 += 4) {
        float a0 = 0.f, a1 = 0.f, a2 = 0.f, a3 = 0.f;
        #pragma unroll 8
        for (int c = 0; c < K; c++) {
            float wv = W[c * NC + j];
            a0 = fmaf(hs[r0 + 0][c], wv, a0);
            a1 = fmaf(hs[r0 + 1][c], wv, a1);
            a2 = fmaf(hs[r0 + 2][c], wv, a2);
            a3 = fmaf(hs[r0 + 3][c], wv, a3);
        }
        g_Zs[(size_t)(row0 + r0 + 0) * NC + j] = g_dinv[row0 + r0 + 0] * a0;
        g_Zs[(size_t)(row0 + r0 + 1) * NC + j] = g_dinv[row0 + r0 + 1] * a1;
        g_Zs[(size_t)(row0 + r0 + 2) * NC + j] = g_dinv[row0 + r0 + 2] * a2;
        g_Zs[(size_t)(row0 + r0 + 3) * NC + j] = g_dinv[row0 + r0 + 3] * a3;
    }
}

// ---------------------------------------------------------------------------
// Kernel 3: Out = epilogue( adj @ Zs )
//   epilogue: val = dinv[i]*(acc + Zs[i,j]) + bias[j]; optional relu
//   BM=64, BK=16, thread tile TM x 8, THREADS = (64/TM)*(BN/8)
// ---------------------------------------------------------------------------
template<int BN, int TM, bool RELU, bool TO_OUT>
__global__ void __launch_bounds__((64 / TM) * (BN / 8))
spmm_kernel(const float* __restrict__ adj,
            const float* __restrict__ bias,
            float* __restrict__ OutParam) {
    const int BM = 64, BK = 16;
    const int TW = BN / 8;                       // thread columns groups
    const int THREADS = (BM / TM) * TW;          // 128 for both configs used
    const int AELEMS = BM * BK / THREADS;        // scalar A loads per thread
    const int BVECS = (BK * BN / 4) / THREADS;   // float4 B loads per thread

    __shared__ float As[2][BK][BM + 4];          // [k][m], +4 pad keeps 16B align
    __shared__ float Bs[2][BK][BN];              // [k][n]

    float* Out = TO_OUT ? OutParam : g_H;
    const float* Zs = g_Zs;

    int tid = threadIdx.x;
    int tx = tid % TW;
    int ty = tid / TW;
    int m0 = blockIdx.x * BM;

    float acc[TM][8];
    #pragma unroll
    for (int u = 0; u < TM; u++)
        #pragma unroll
        for (int v = 0; v < 8; v++) acc[u][v] = 0.f;

    float  astage[AELEMS];
    float4 bstage[BVECS];

    // ---- prologue: tile 0 -> smem buffer 0 ----
    #pragma unroll
    for (int t = 0; t < AELEMS; t++) {
        int idx = tid + t * THREADS;
        astage[t] = adj[(size_t)(m0 + (idx >> 4)) * GN + (idx & 15)];
    }
    #pragma unroll
    for (int t = 0; t < BVECS; t++) {
        int idx = tid + t * THREADS;
        bstage[t] = *reinterpret_cast<const float4*>(
            Zs + (size_t)(idx / (BN / 4)) * BN + (idx % (BN / 4)) * 4);
    }
    #pragma unroll
    for (int t = 0; t < AELEMS; t++) {
        int idx = tid + t * THREADS;
        As[0][idx & 15][idx >> 4] = astage[t];
    }
    #pragma unroll
    for (int t = 0; t < BVECS; t++) {
        int idx = tid + t * THREADS;
        *reinterpret_cast<float4*>(&Bs[0][idx / (BN / 4)][(idx % (BN / 4)) * 4]) = bstage[t];
    }
    __syncthreads();

    const int NT = GN / BK;   // 512 K-tiles
    #pragma unroll 1
    for (int kt = 0; kt < NT; kt++) {
        int cur = kt & 1;
        // prefetch next tile into registers (overlaps with FMA below)
        if (kt < NT - 1) {
            int k0 = (kt + 1) * BK;
            #pragma unroll
            for (int t = 0; t < AELEMS; t++) {
                int idx = tid + t * THREADS;
                astage[t] = adj[(size_t)(m0 + (idx >> 4)) * GN + k0 + (idx & 15)];
            }
            #pragma unroll
            for (int t = 0; t < BVECS; t++) {
                int idx = tid + t * THREADS;
                bstage[t] = *reinterpret_cast<const float4*>(
                    Zs + (size_t)(k0 + idx / (BN / 4)) * BN + (idx % (BN / 4)) * 4);
            }
        }
        // compute on current buffer
        #pragma unroll
        for (int kk = 0; kk < BK; kk++) {
            float a[8], b[8];
            float4 af0 = *reinterpret_cast<const float4*>(&As[cur][kk][ty * TM]);
            a[0] = af0.x; a[1] = af0.y; a[2] = af0.z; a[3] = af0.w;
            if constexpr (TM == 8) {
                float4 af1 = *reinterpret_cast<const float4*>(&As[cur][kk][ty * TM + 4]);
                a[4] = af1.x; a[5] = af1.y; a[6] = af1.z; a[7] = af1.w;
            }
            float4 bf0 = *reinterpret_cast<const float4*>(&Bs[cur][kk][tx * 8]);
            float4 bf1 = *reinterpret_cast<const float4*>(&Bs[cur][kk][tx * 8 + 4]);
            b[0] = bf0.x; b[1] = bf0.y; b[2] = bf0.z; b[3] = bf0.w;
            b[4] = bf1.x; b[5] = bf1.y; b[6] = bf1.z; b[7] = bf1.w;
            #pragma unroll
            for (int u = 0; u < TM; u++)
                #pragma unroll
                for (int v = 0; v < 8; v++)
                    acc[u][v] = fmaf(a[u], b[v], acc[u][v]);
        }
        // stage -> next buffer
        if (kt < NT - 1) {
            int nxt = cur ^ 1;
            #pragma unroll
            for (int t = 0; t < AELEMS; t++) {
                int idx = tid + t * THREADS;
                As[nxt][idx & 15][idx >> 4] = astage[t];
            }
            #pragma unroll
            for (int t = 0; t < BVECS; t++) {
                int idx = tid + t * THREADS;
                *reinterpret_cast<float4*>(&Bs[nxt][idx / (BN / 4)][(idx % (BN / 4)) * 4]) = bstage[t];
            }
        }
        __syncthreads();
    }

    // ---- fused epilogue: An@Z = dinv[i]*(adj@Zs + Zs[i]) , + bias, relu ----
    #pragma unroll
    for (int u = 0; u < TM; u++) {
        int row = m0 + ty * TM + u;
        float di = g_dinv[row];
        #pragma unroll
        for (int v = 0; v < 8; v++) {
            int col = tx * 8 + v;
            float val = fmaf(di, acc[u][v] + Zs[(size_t)row * BN + col], bias[col]);
            if (RELU) val = fmaxf(val, 0.f);
            Out[(size_t)row * BN + col] = val;
        }
    }
}

// ---------------------------------------------------------------------------
// Launch: 3-layer GCN
//   inputs: 0:x 1:adj 2:W0 3:b0 4:W1 5:b1 6:W2 7:b2 ; output fp32 [8192,64]
// ---------------------------------------------------------------------------
extern "C" void kernel_launch(void* const* d_in, const int* in_sizes, int n_in,
                              void* d_out, int out_size) {
    const float* x   = (const float*)d_in[0];
    const float* adj = (const float*)d_in[1];
    const float* W0  = (const float*)d_in[2];
    const float* b0  = (const float*)d_in[3];
    const float* W1  = (const float*)d_in[4];
    const float* b1  = (const float*)d_in[5];
    const float* W2  = (const float*)d_in[6];
    const float* b2  = (const float*)d_in[7];
    float* out = (float*)d_out;

    rowsum_kernel<<<GN, 256>>>(adj);

    // layer 0: h = relu(An @ (x@W0) + b0)
    feat_gemm_kernel<64, 128, true><<<GN / 32, 128>>>(x, W0);
    spmm_kernel<128, 8, true, false><<<GN / 64, 128>>>(adj, b0, nullptr);

    // layer 1: h = relu(An @ (h@W1) + b1)
    feat_gemm_kernel<128, 128, false><<<GN / 32, 128>>>(nullptr, W1);
    spmm_kernel<128, 8, true, false><<<GN / 64, 128>>>(adj, b1, nullptr);

    // layer 2: out = An @ (h@W2) + b2
    feat_gemm_kernel<128, 64, false><<<GN / 32, 64>>>(nullptr, W2);
    spmm_kernel<64, 4, false, true><<<GN / 64, 128>>>(adj, b2, out);
}

// round 5
// speedup vs baseline: 3.7829x; 3.7829x over previous
#include <cuda_runtime.h>
#include <cuda_bf16.h>
#include <cstdint>

#define GN 8192

// ---------------------------------------------------------------------------
// Device-global scratch (allocation-free per harness rules)
// ---------------------------------------------------------------------------
__device__ float g_dinv[GN];
__device__ __nv_bfloat16 g_adj_hi[(size_t)GN * GN];   // 128 MB
__device__ __nv_bfloat16 g_adj_lo[(size_t)GN * GN];   // 128 MB
__device__ float g_Zs[GN * 128];                      // dinv ⊙ (h@W), fp32 [row][col]
__device__ __nv_bfloat16 g_Bhi[128 * GN];             // Zs^T hi  [n][k]  (col-major B)
__device__ __nv_bfloat16 g_Blo[128 * GN];             // Zs^T lo  [n][k]
__device__ float g_H[GN * 128];                       // layer activations fp32

// ---------------------------------------------------------------------------
// PTX helpers (compute_103-safe: cp.async + ldmatrix + mma.sync only)
// ---------------------------------------------------------------------------
__device__ __forceinline__ uint32_t smem_u32(const void* p) {
    uint32_t a;
    asm("{ .reg .u64 t; cvta.to.shared.u64 t, %1; cvt.u32.u64 %0, t; }" : "=r"(a) : "l"(p));
    return a;
}
__device__ __forceinline__ void cp16(uint32_t dst, const void* src) {
    asm volatile("cp.async.cg.shared.global [%0], [%1], 16;" :: "r"(dst), "l"(src));
}
__device__ __forceinline__ void cp_commit() { asm volatile("cp.async.commit_group;" ::: "memory"); }
template<int N>
__device__ __forceinline__ void cp_wait() { asm volatile("cp.async.wait_group %0;" :: "n"(N) : "memory"); }

__device__ __forceinline__ void ldsm4(uint32_t* r, uint32_t addr) {
    asm volatile("ldmatrix.sync.aligned.m8n8.x4.shared.b16 {%0,%1,%2,%3}, [%4];"
                 : "=r"(r[0]), "=r"(r[1]), "=r"(r[2]), "=r"(r[3]) : "r"(addr));
}
__device__ __forceinline__ void mma_bf16(float* d, const uint32_t* a, const uint32_t* b) {
    asm volatile("mma.sync.aligned.m16n8k16.row.col.f32.bf16.bf16.f32 "
                 "{%0,%1,%2,%3}, {%4,%5,%6,%7}, {%8,%9}, {%0,%1,%2,%3};"
                 : "+f"(d[0]), "+f"(d[1]), "+f"(d[2]), "+f"(d[3])
                 : "r"(a[0]), "r"(a[1]), "r"(a[2]), "r"(a[3]), "r"(b[0]), "r"(b[1]));
}

// ---------------------------------------------------------------------------
// Kernel 1: rowsum + fp32 -> bf16 hi/lo split of adj (fused single pass)
// ---------------------------------------------------------------------------
__global__ void __launch_bounds__(256) convert_rowsum(const float* __restrict__ adj) {
    int row = blockIdx.x;
    int tid = threadIdx.x;
    const float4* src = reinterpret_cast<const float4*>(adj + (size_t)row * GN);
    uint2* dhi = reinterpret_cast<uint2*>(g_adj_hi + (size_t)row * GN);
    uint2* dlo = reinterpret_cast<uint2*>(g_adj_lo + (size_t)row * GN);
    float s = 0.f;
    for (int i = tid; i < GN / 4; i += 256) {
        float4 v = src[i];
        s += (v.x + v.y) + (v.z + v.w);
        __nv_bfloat16 h0 = __float2bfloat16(v.x);
        __nv_bfloat16 h1 = __float2bfloat16(v.y);
        __nv_bfloat16 h2 = __float2bfloat16(v.z);
        __nv_bfloat16 h3 = __float2bfloat16(v.w);
        __nv_bfloat16 l0 = __float2bfloat16(v.x - __bfloat162float(h0));
        __nv_bfloat16 l1 = __float2bfloat16(v.y - __bfloat162float(h1));
        __nv_bfloat16 l2 = __float2bfloat16(v.z - __bfloat162float(h2));
        __nv_bfloat16 l3 = __float2bfloat16(v.w - __bfloat162float(h3));
        uint2 hu, lu;
        hu.x = (uint32_t)__bfloat16_as_ushort(h0) | ((uint32_t)__bfloat16_as_ushort(h1) << 16);
        hu.y = (uint32_t)__bfloat16_as_ushort(h2) | ((uint32_t)__bfloat16_as_ushort(h3) << 16);
        lu.x = (uint32_t)__bfloat16_as_ushort(l0) | ((uint32_t)__bfloat16_as_ushort(l1) << 16);
        lu.y = (uint32_t)__bfloat16_as_ushort(l2) | ((uint32_t)__bfloat16_as_ushort(l3) << 16);
        dhi[i] = hu;
        dlo[i] = lu;
    }
    __shared__ float red[8];
    #pragma unroll
    for (int o = 16; o; o >>= 1) s += __shfl_down_sync(0xffffffffu, s, o);
    if ((tid & 31) == 0) red[tid >> 5] = s;
    __syncthreads();
    if (tid == 0) {
        float t = 0.f;
        #pragma unroll
        for (int w = 0; w < 8; w++) t += red[w];
        g_dinv[row] = rsqrtf(t + 1.0f);
    }
}

// ---------------------------------------------------------------------------
// Kernel 2: Zs = dinv ⊙ (Hin @ W); writes fp32 Zs + bf16 hi/lo transposed [n][k]
// ---------------------------------------------------------------------------
template<int K, int NC, bool FROM_PARAM>
__global__ void __launch_bounds__(256) feat_gemm(const float* __restrict__ Xin,
                                                 const float* __restrict__ W) {
    constexpr int CW = NC / 16;       // cols per thread (8 or 4)
    __shared__ float hs[64][K];
    __shared__ float ws[16][NC];
    const float* Hin = FROM_PARAM ? Xin : g_H;
    int tid = threadIdx.x;
    int r0 = blockIdx.x * 64;
    int tx = tid & 15, ty = tid >> 4;

    {   // stage 64 input rows
        const float4* s4 = reinterpret_cast<const float4*>(Hin + (size_t)r0 * K);
        float4* d4 = reinterpret_cast<float4*>(&hs[0][0]);
        for (int i = tid; i < 64 * K / 4; i += 256) d4[i] = s4[i];
    }
    float acc[4][CW];
    #pragma unroll
    for (int r = 0; r < 4; r++)
        #pragma unroll
        for (int c = 0; c < CW; c++) acc[r][c] = 0.f;

    for (int kc = 0; kc < K / 16; kc++) {
        __syncthreads();
        {   // stage 16 x NC weight chunk
            const float4* s4 = reinterpret_cast<const float4*>(W + kc * 16 * NC);
            float4* d4 = reinterpret_cast<float4*>(&ws[0][0]);
            for (int i = tid; i < 16 * NC / 4; i += 256) d4[i] = s4[i];
        }
        __syncthreads();
        #pragma unroll
        for (int k = 0; k < 16; k++) {
            float a0 = hs[ty * 4 + 0][kc * 16 + k];
            float a1 = hs[ty * 4 + 1][kc * 16 + k];
            float a2 = hs[ty * 4 + 2][kc * 16 + k];
            float a3 = hs[ty * 4 + 3][kc * 16 + k];
            #pragma unroll
            for (int c = 0; c < CW; c++) {
                float w = ws[k][c * 16 + tx];   // interleaved: conflict-free
                acc[0][c] = fmaf(a0, w, acc[0][c]);
                acc[1][c] = fmaf(a1, w, acc[1][c]);
                acc[2][c] = fmaf(a2, w, acc[2][c]);
                acc[3][c] = fmaf(a3, w, acc[3][c]);
            }
        }
    }
    #pragma unroll
    for (int r = 0; r < 4; r++) {
        int row = r0 + ty * 4 + r;
        float di = g_dinv[row];
        #pragma unroll
        for (int c = 0; c < CW; c++) {
            int col = c * 16 + tx;
            float z = di * acc[r][c];
            g_Zs[(size_t)row * NC + col] = z;
            __nv_bfloat16 h = __float2bfloat16(z);
            __nv_bfloat16 l = __float2bfloat16(z - __bfloat162float(h));
            g_Bhi[(size_t)col * GN + row] = h;
            g_Blo[(size_t)col * GN + row] = l;
        }
    }
}

// ---------------------------------------------------------------------------
// Kernel 3: split-precision HMMA SpMM with fused epilogue
//   Out = [relu]( dinv[i]*( adj@Zs + Zs[i,:] ) + bias )
//   BM=64 (128 CTAs), BN = full width, BK=32, 4-stage cp.async pipeline.
//   3 accumulating passes: Ahi*Bhi + Ahi*Blo + Alo*Bhi   (drop Alo*Blo ~2^-18)
//   smem tile layout: bf16 [row][32] rows of 4x16B chunks, chunk' = c ^ ((row>>1)&3)
// ---------------------------------------------------------------------------
template<int BN, bool RELU, bool TO_OUT>
__global__ void __launch_bounds__(256) spmm_hmma(const float* __restrict__ bias,
                                                 float* __restrict__ OutParam) {
    constexpr int BM = 64, BK = 32;
    constexpr int NT = GN / BK;               // 256 k-tiles
    constexpr int ASZ = BM * BK * 2;          // 4 KB per A plane
    constexpr int BSZ = BN * BK * 2;          // per B plane
    constexpr int STAGE = 2 * ASZ + 2 * BSZ;  // hi+lo for A and B
    constexpr int WN = BN / 4;                // warp n-extent (warp grid 2x4)
    constexpr int NF = WN / 8;                // n8 fragments per warp

    extern __shared__ char smem[];
    const uint32_t sb0 = smem_u32(smem);

    const int tid = threadIdx.x;
    const int lane = tid & 31;
    const int warp = tid >> 5;
    const int wm = warp >> 2;                 // 0..1
    const int wn = warp & 3;                  // 0..3
    const int m0 = blockIdx.x * BM;
    const int n0c = wn * WN;

    float acc[2][NF][4];
    #pragma unroll
    for (int mt = 0; mt < 2; mt++)
        #pragma unroll
        for (int nf = 0; nf < NF; nf++)
            #pragma unroll
            for (int q = 0; q < 4; q++) acc[mt][nf][q] = 0.f;

    auto issue = [&](int kt) {
        if (kt < NT) {
            const uint32_t sb = sb0 + (kt & 3) * STAGE;
            const int k0 = kt * BK;
            {   // A: 64 rows x 4 chunks = 256 -> 1 chunk/thread/plane
                int row = tid >> 2, c = tid & 3;
                uint32_t so = row * 64 + ((c ^ ((row >> 1) & 3)) << 4);
                size_t go = (size_t)(m0 + row) * GN + k0 + c * 8;
                cp16(sb + so, g_adj_hi + go);
                cp16(sb + ASZ + so, g_adj_lo + go);
            }
            #pragma unroll
            for (int j = 0; j < BN / 64; j++) {  // B: BN rows x 4 chunks
                int id = tid + j * 256;
                int row = id >> 2, c = id & 3;
                uint32_t so = row * 64 + ((c ^ ((row >> 1) & 3)) << 4);
                size_t go = (size_t)row * GN + k0 + c * 8;
                cp16(sb + 2 * ASZ + so, g_Bhi + go);
                cp16(sb + 2 * ASZ + BSZ + so, g_Blo + go);
            }
        }
        cp_commit();
    };

    issue(0); issue(1); issue(2);

    #pragma unroll 1
    for (int kt = 0; kt < NT; kt++) {
        cp_wait<2>();          // tile kt resident
        __syncthreads();
        issue(kt + 3);         // refill slot (kt+3)&3 (== (kt-1)&3, done last iter)

        const uint32_t sb = sb0 + (kt & 3) * STAGE;
        #pragma unroll
        for (int ks = 0; ks < 2; ks++) {       // two k16 steps per BK=32
            const int kc = ks * 2;             // base 16B-chunk of this k16
            // A fragments: [plane][mtile][4]
            uint32_t af[2][2][4];
            #pragma unroll
            for (int mt = 0; mt < 2; mt++) {
                int row = wm * 32 + mt * 16 + (lane & 15);
                int ch = (kc + (lane >> 4)) ^ ((row >> 1) & 3);
                uint32_t ad = sb + row * 64 + ch * 16;
                ldsm4(af[0][mt], ad);
                ldsm4(af[1][mt], ad + ASZ);
            }
            // B fragments: [plane][nf][2]
            uint32_t bf[2][NF][2];
            #pragma unroll
            for (int bt = 0; bt < NF / 2; bt++) {
                int row = n0c + bt * 16 + (lane & 7) + ((lane >> 4) << 3);
                int ch = (kc + ((lane >> 3) & 1)) ^ ((row >> 1) & 3);
                uint32_t ad = sb + 2 * ASZ + row * 64 + ch * 16;
                uint32_t t[4];
                ldsm4(t, ad);                  // hi plane: two n8 frags
                bf[0][2 * bt][0] = t[0]; bf[0][2 * bt][1] = t[1];
                bf[0][2 * bt + 1][0] = t[2]; bf[0][2 * bt + 1][1] = t[3];
                ldsm4(t, ad + BSZ);            // lo plane
                bf[1][2 * bt][0] = t[0]; bf[1][2 * bt][1] = t[1];
                bf[1][2 * bt + 1][0] = t[2]; bf[1][2 * bt + 1][1] = t[3];
            }
            // three accumulating passes: hi*hi, hi*lo, lo*hi
            #pragma unroll
            for (int mt = 0; mt < 2; mt++)
                #pragma unroll
                for (int nf = 0; nf < NF; nf++) {
                    mma_bf16(acc[mt][nf], af[0][mt], bf[0][nf]);
                    mma_bf16(acc[mt][nf], af[0][mt], bf[1][nf]);
                    mma_bf16(acc[mt][nf], af[1][mt], bf[0][nf]);
                }
        }
    }

    // ---- fused epilogue straight from accumulators ----
    float* Out = TO_OUT ? OutParam : g_H;
    const int gr = lane >> 2;
    const int gc = (lane & 3) * 2;
    #pragma unroll
    for (int mt = 0; mt < 2; mt++) {
        #pragma unroll
        for (int half = 0; half < 2; half++) {
            int row = m0 + wm * 32 + mt * 16 + half * 8 + gr;
            float di = g_dinv[row];
            #pragma unroll
            for (int nf = 0; nf < NF; nf++) {
                int col = n0c + nf * 8 + gc;
                float2 z = *reinterpret_cast<const float2*>(&g_Zs[(size_t)row * BN + col]);
                float v0 = fmaf(di, acc[mt][nf][half * 2 + 0] + z.x, bias[col]);
                float v1 = fmaf(di, acc[mt][nf][half * 2 + 1] + z.y, bias[col + 1]);
                if (RELU) { v0 = fmaxf(v0, 0.f); v1 = fmaxf(v1, 0.f); }
                *reinterpret_cast<float2*>(&Out[(size_t)row * BN + col]) = make_float2(v0, v1);
            }
        }
    }
}

// ---------------------------------------------------------------------------
// Launch: 3-layer GCN
// ---------------------------------------------------------------------------
extern "C" void kernel_launch(void* const* d_in, const int* in_sizes, int n_in,
                              void* d_out, int out_size) {
    const float* x   = (const float*)d_in[0];
    const float* adj = (const float*)d_in[1];
    const float* W0  = (const float*)d_in[2];
    const float* b0  = (const float*)d_in[3];
    const float* W1  = (const float*)d_in[4];
    const float* b1  = (const float*)d_in[5];
    const float* W2  = (const float*)d_in[6];
    const float* b2  = (const float*)d_in[7];
    float* out = (float*)d_out;

    const int SM128 = 4 * (2 * 64 * 32 * 2 + 2 * 128 * 32 * 2);  // 98304
    const int SM64  = 4 * (2 * 64 * 32 * 2 + 2 * 64 * 32 * 2);   // 65536
    cudaFuncSetAttribute(spmm_hmma<128, true, false>,
                         cudaFuncAttributeMaxDynamicSharedMemorySize, SM128);
    cudaFuncSetAttribute(spmm_hmma<64, false, true>,
                         cudaFuncAttributeMaxDynamicSharedMemorySize, SM64);

    convert_rowsum<<<GN, 256>>>(adj);

    // layer 0: h = relu(An @ (x@W0) + b0)
    feat_gemm<64, 128, true><<<GN / 64, 256>>>(x, W0);
    spmm_hmma<128, true, false><<<GN / 64, 256, SM128>>>(b0, nullptr);

    // layer 1: h = relu(An @ (h@W1) + b1)
    feat_gemm<128, 128, false><<<GN / 64, 256>>>(nullptr, W1);
    spmm_hmma<128, true, false><<<GN / 64, 256, SM128>>>(b1, nullptr);

    // layer 2: out = An @ (h@W2) + b2
    feat_gemm<128, 64, false><<<GN / 64, 256>>>(nullptr, W2);
    spmm_hmma<64, false, true><<<GN / 64, 256, SM64>>>(b2, out);
}